// round 17
// baseline (speedup 1.0000x reference)
#include <cuda_runtime.h>
#include <cuda_fp16.h>
#include <math.h>
#include <stdint.h>

#define BSZ 4
#define LEN 1024
#define DM 1024
#define NH 16
#define NAA 25
#define LOG2E 1.44269504f

// ---------------- scratch (static device globals; no allocation) ----------------
__device__ float g_bias[BSZ * LEN * LEN];       // pre-scaled by log2(e)
__device__ float g_proj[BSZ * LEN * NH];
__device__ __half g_a[4096 * 1024];             // x fp16, later ctx fp16
__device__ __half g_w[4096 * 1024];             // rows 0-3071 = Wq,Wk,Wv; 3072-4095 = Wo
__device__ __half g_qkv[BSZ * LEN * 3 * DM];    // fp16 (q pre-scaled by 0.125*log2e)

static __device__ __forceinline__ uint32_t smem_u32(const void* p) {
    uint32_t a;
    asm("{ .reg .u64 t; cvta.to.shared.u64 t, %1; cvt.u32.u64 %0, t; }" : "=r"(a) : "l"(p));
    return a;
}
static __device__ __forceinline__ uint32_t pack_h2(float x, float y) {
    __half2 h = __floats2half2_rn(x, y);
    uint32_t u;
    __builtin_memcpy(&u, &h, 4);
    return u;
}

#define LDSM4(r, addr)                                                            \
    asm volatile("ldmatrix.sync.aligned.m8n8.x4.shared.b16 {%0,%1,%2,%3}, [%4];"  \
                 : "=r"((r)[0]), "=r"((r)[1]), "=r"((r)[2]), "=r"((r)[3])         \
                 : "r"(addr))
#define LDSM4T(r, addr)                                                                \
    asm volatile("ldmatrix.sync.aligned.m8n8.x4.trans.shared.b16 {%0,%1,%2,%3}, [%4];" \
                 : "=r"((r)[0]), "=r"((r)[1]), "=r"((r)[2]), "=r"((r)[3])              \
                 : "r"(addr))
#define MMA16816(d, a, b)                                                         \
    asm volatile("mma.sync.aligned.m16n8k16.row.col.f32.f16.f16.f32 "             \
                 "{%0,%1,%2,%3}, {%4,%5,%6,%7}, {%8,%9}, {%0,%1,%2,%3};"          \
                 : "+f"((d)[0]), "+f"((d)[1]), "+f"((d)[2]), "+f"((d)[3])         \
                 : "r"((a)[0]), "r"((a)[1]), "r"((a)[2]), "r"((a)[3]),            \
                   "r"((b)[0]), "r"((b)[1]))
#define CPA16(d, g) asm volatile("cp.async.cg.shared.global [%0], [%1], 16;" :: "r"(d), "l"(g))

// ---------------- fp32 -> fp16 convert ----------------
__global__ __launch_bounds__(256)
void conv_kernel(const float4* __restrict__ a, __half2* __restrict__ w, int n4) {
    int i = blockIdx.x * blockDim.x + threadIdx.x;
    if (i >= n4) return;
    float4 v = a[i];
    w[2 * i]     = __floats2half2_rn(v.x, v.y);
    w[2 * i + 1] = __floats2half2_rn(v.z, v.w);
}

__global__ __launch_bounds__(256)
void conv4_kernel(const float4* __restrict__ a0, const float4* __restrict__ a1,
                  const float4* __restrict__ a2, const float4* __restrict__ a3,
                  __half2* __restrict__ w) {
    const int tensor = blockIdx.y;
    const float4* a = (tensor == 0) ? a0 : (tensor == 1) ? a1 : (tensor == 2) ? a2 : a3;
    int i = blockIdx.x * blockDim.x + threadIdx.x;
    float4 v = a[i];
    __half2* dst = w + (size_t)tensor * 524288;
    dst[2 * i]     = __floats2half2_rn(v.x, v.y);
    dst[2 * i + 1] = __floats2half2_rn(v.z, v.w);
}

// ---------------- HMMA fp16 1-pass GEMM: C[M,N] = A[M,K] @ W[N,K]^T ----------------
// Cf!=0: fp32 out (+bias). Else fp16 out; cols < qcols scaled by 0.125*log2e.
#define RS 80
#define TEN 10240
#define STG (2 * TEN)
#define NCH 32

__global__ __launch_bounds__(256, 1)
void gemm_mma(const __half* __restrict__ A, const __half* __restrict__ W,
              const float* __restrict__ bias, float* __restrict__ Cf,
              __half* __restrict__ Ch, int N, int wrow0, int m_off, int qcols) {
    extern __shared__ char sm[];
    const uint32_t sb = smem_u32(sm);
    const int t = threadIdx.x, wid = t >> 5, lane = t & 31;
    const int m0 = (blockIdx.y << 7) + m_off, n0 = blockIdx.x << 7;
    const int wm = wid & 1, wn = wid >> 1;

    const char* gsrc[2];
    gsrc[0] = (const char*)(A + (size_t)m0 * 1024);
    gsrc[1] = (const char*)(W + (size_t)(wrow0 + n0) * 1024);

    const int mat = lane >> 3, lr = lane & 7;
    const uint32_t a_off = (uint32_t)((((mat & 1) << 3) + lr) * RS + ((mat >> 1) << 4));
    const uint32_t b_off = (uint32_t)((((mat >> 1) << 3) + lr) * RS + ((mat & 1) << 4));

    auto load_stage = [&](int st, int c) {
        uint32_t dbase = sb + st * STG;
#pragma unroll
        for (int q = 0; q < 2; q++) {
#pragma unroll
            for (int h = 0; h < 2; h++) {
                int idx = t + h * 256;
                int row = idx >> 2, seg = idx & 3;
                const char* g = gsrc[q] + (size_t)row * 2048 + c * 64 + seg * 16;
                CPA16(dbase + q * TEN + row * RS + seg * 16, g);
            }
        }
        asm volatile("cp.async.commit_group;" ::: "memory");
    };

    float acc[4][4][4];
#pragma unroll
    for (int i = 0; i < 4; i++)
#pragma unroll
        for (int j = 0; j < 4; j++)
#pragma unroll
            for (int k = 0; k < 4; k++) acc[i][j][k] = 0.f;

    load_stage(0, 0);

    for (int c = 0; c < NCH; c++) {
        const int st = c & 1;
        if (c + 1 < NCH) {
            load_stage(st ^ 1, c + 1);
            asm volatile("cp.async.wait_group 1;" ::: "memory");
        } else {
            asm volatile("cp.async.wait_group 0;" ::: "memory");
        }
        __syncthreads();

        const uint32_t abase = sb + st * STG;
#pragma unroll
        for (int k16 = 0; k16 < 2; k16++) {
            uint32_t ah[4][4], bfrag[4][2];
#pragma unroll
            for (int mt = 0; mt < 4; mt++)
                LDSM4(ah[mt], abase + (wm * 64 + mt * 16) * RS + k16 * 32 + a_off);
#pragma unroll
            for (int p = 0; p < 2; p++) {
                uint32_t r[4];
                LDSM4(r, abase + TEN + (wn * 32 + p * 16) * RS + k16 * 32 + b_off);
                bfrag[2 * p][0] = r[0]; bfrag[2 * p][1] = r[1];
                bfrag[2 * p + 1][0] = r[2]; bfrag[2 * p + 1][1] = r[3];
            }
#pragma unroll
            for (int mt = 0; mt < 4; mt++)
#pragma unroll
                for (int nt = 0; nt < 4; nt++)
                    MMA16816(acc[mt][nt], ah[mt], bfrag[nt]);
        }
        __syncthreads();
    }

    const int qrow = lane >> 2, qcol = (lane & 3) * 2;
#pragma unroll
    for (int mt = 0; mt < 4; mt++) {
        const int r0 = m0 + wm * 64 + mt * 16 + qrow;
#pragma unroll
        for (int nt = 0; nt < 4; nt++) {
            const int col = n0 + wn * 32 + nt * 8 + qcol;
            if (Cf) {
                float bx = 0.f, by = 0.f;
                if (bias) { bx = bias[col]; by = bias[col + 1]; }
                *(float2*)(Cf + (size_t)r0 * N + col) =
                    make_float2(acc[mt][nt][0] + bx, acc[mt][nt][1] + by);
                *(float2*)(Cf + (size_t)(r0 + 8) * N + col) =
                    make_float2(acc[mt][nt][2] + bx, acc[mt][nt][3] + by);
            } else {
                const float s = (col < qcols) ? (0.125f * LOG2E) : 1.0f;
#pragma unroll
                for (int rr = 0; rr < 2; rr++) {
                    size_t off = (size_t)(r0 + rr * 8) * N + col;
                    *(uint32_t*)(Ch + off) =
                        pack_h2(acc[mt][nt][2 * rr] * s, acc[mt][nt][2 * rr + 1] * s);
                }
            }
        }
    }
}

// ---------------- proj = secondary_structure @ ss_w^T ----------------
__global__ __launch_bounds__(256) void proj_kernel(const float* __restrict__ ss,
                                                   const float* __restrict__ ss_w,
                                                   float* __restrict__ proj) {
    __shared__ float w[NH][8];
    int t = threadIdx.x;
    if (t < NH * 8) w[t / 8][t % 8] = ss_w[t];
    __syncthreads();
    int idx = blockIdx.x * blockDim.x + t;
    int h = idx & 15;
    int bl = idx >> 4;
    const float* s = ss + bl * 8;
    float acc = 0.f;
#pragma unroll
    for (int c = 0; c < 8; c++) acc += s[c] * w[h][c];
    proj[idx] = acc;
}

// ---------------- shared bias tensor (pre-scaled by log2e; dist_bias dropped) ----------------
__global__ __launch_bounds__(1024) void bias_kernel(const float* __restrict__ pf,
                                                    const int* __restrict__ ids,
                                                    const float* __restrict__ inter_mat,
                                                    const float* __restrict__ projp,
                                                    const float* __restrict__ physics_scale,
                                                    const float* __restrict__ distance_decay,
                                                    float* __restrict__ biasout, int b_off) {
    __shared__ float sym[NAA * NAA];
    __shared__ float pi[32][17];
    __shared__ float pj[32][17];
    __shared__ int idi[32], idj[32];

    const int b = blockIdx.z + b_off;
    const int i0 = blockIdx.y * 32;
    const int j0 = blockIdx.x * 32;
    const int t = threadIdx.y * 32 + threadIdx.x;

    for (int s = t; s < NAA * NAA; s += 1024) {
        int r = s / NAA, c = s % NAA;
        sym[s] = 0.5f * (inter_mat[r * NAA + c] + inter_mat[c * NAA + r]);
    }
    if (t < 32)       idi[t]      = min(max(ids[b * LEN + i0 + t], 0), NAA - 1);
    else if (t < 64)  idj[t - 32] = min(max(ids[b * LEN + j0 + (t - 32)], 0), NAA - 1);
    if (t < 512) {
        int r = t / 16, c = t % 16;
        pi[r][c] = projp[(b * LEN + i0 + r) * NH + c];
    } else {
        int u = t - 512;
        int r = u / 16, c = u % 16;
        pj[r][c] = projp[(b * LEN + j0 + r) * NH + c];
    }
    __syncthreads();

    const int i = threadIdx.y, j = threadIdx.x;
    float decay = fminf(fmaxf(distance_decay[0], 0.1f), 5.0f);
    float sig = 1.0f / (1.0f + __expf(-physics_scale[0]));

    float d = pf[(size_t)b * LEN * LEN + (size_t)(i0 + i) * LEN + (j0 + j)];
    d = fminf(fmaxf(d, 0.1f), 50.0f);
    float pen = -__powf(d, decay) * sig;

    float it = sym[idi[i] * NAA + idj[j]] *
               (1.0f / (1.0f + fabsf((float)(i0 + i) - (float)(j0 + j))));

    float dot = 0.f;
#pragma unroll
    for (int hh = 0; hh < NH; hh++) dot += pi[i][hh] * pj[j][hh];
    float st = 1.0f / (1.0f + __expf(-dot)) - 0.5f;

    biasout[(size_t)b * LEN * LEN + (size_t)(i0 + i) * LEN + (j0 + j)] =
        (pen + it + st) * LOG2E;
}

// ---------------- HMMA fp16 flash attention: j-tile 64, 2 CTAs/SM ----------------
// scores already in log2 domain (q pre-scaled, bias pre-scaled) -> exp2f softmax.
#define ARS 144
#define QB (128 * ARS)
#define KVT64 (64 * ARS)
#define KVSTG (2 * KVT64)
#define ATTN_SMEM (QB + 2 * KVSTG)   // 55296

__global__ __launch_bounds__(256, 2)
void attn_mma(const __half* __restrict__ qkv,
              const float* __restrict__ biasp, __half* __restrict__ ctx, int b_off) {
    extern __shared__ char sm[];
    const uint32_t sb = smem_u32(sm);
    const int t = threadIdx.x, wid = t >> 5, lane = t & 31;
    const int i0 = blockIdx.x * 128, h = blockIdx.y, b = blockIdx.z + b_off;

    const int mat = lane >> 3, lr = lane & 7;
    const uint32_t a_off = (uint32_t)((((mat & 1) << 3) + lr) * ARS + ((mat >> 1) << 4));
    const uint32_t b_offd = (uint32_t)((((mat >> 1) << 3) + lr) * ARS + ((mat & 1) << 4));
    const uint32_t v_off = (uint32_t)((lane & 15) * ARS + ((lane >> 4) << 4));

#pragma unroll
    for (int i = 0; i < 4; i++) {
        int idx = t + i * 256;
        int row = idx >> 3, seg = idx & 7;
        const char* g = (const char*)(qkv + (size_t)(b * LEN + i0 + row) * 3072 + h * 64) + seg * 16;
        CPA16(sb + row * ARS + seg * 16, g);
    }
    auto load_kv = [&](int st, int jt) {
        int j0 = jt * 64;
#pragma unroll
        for (int i = 0; i < 4; i++) {
            int idx = t + i * 256;
            int tensor = idx >> 9;                 // 0 Kh, 1 Vh
            int row = (idx >> 3) & 63;
            int seg = idx & 7;
            int coloff = (tensor ? 2048 : 1024) + h * 64;
            const char* g = (const char*)(qkv + (size_t)(b * LEN + j0 + row) * 3072 + coloff) + seg * 16;
            CPA16(sb + QB + st * KVSTG + tensor * KVT64 + row * ARS + seg * 16, g);
        }
        asm volatile("cp.async.commit_group;" ::: "memory");
    };
    load_kv(0, 0);

    float O[8][4];
#pragma unroll
    for (int f = 0; f < 8; f++)
#pragma unroll
        for (int k = 0; k < 4; k++) O[f][k] = 0.f;
    float m0r = -3.0e38f, m1r = -3.0e38f, l0 = 0.f, l1 = 0.f;

    const int r0 = lane >> 2, c0 = (lane & 3) * 2;
    const float* bp = biasp + ((size_t)b * LEN + i0 + wid * 16) * LEN;

    for (int jt = 0; jt < 16; jt++) {
        const int st = jt & 1;
        float2 bpre[8][2];
        {
            const float* bj = bp + jt * 64 + c0;
#pragma unroll
            for (int f = 0; f < 8; f++) {
                bpre[f][0] = *(const float2*)(bj + (size_t)r0 * LEN + f * 8);
                bpre[f][1] = *(const float2*)(bj + (size_t)(r0 + 8) * LEN + f * 8);
            }
        }
        if (jt + 1 < 16) {
            load_kv(st ^ 1, jt + 1);
            asm volatile("cp.async.wait_group 1;" ::: "memory");
        } else {
            asm volatile("cp.async.wait_group 0;" ::: "memory");
        }
        __syncthreads();

        float sacc[8][4];
#pragma unroll
        for (int f = 0; f < 8; f++)
#pragma unroll
            for (int k = 0; k < 4; k++) sacc[f][k] = 0.f;

        const uint32_t kb = sb + QB + st * KVSTG;
#pragma unroll
        for (int kk = 0; kk < 4; kk++) {
            uint32_t a[4];
            LDSM4(a, sb + (wid * 16) * ARS + kk * 32 + a_off);
#pragma unroll
            for (int p = 0; p < 4; p++) {
                uint32_t rh[4];
                LDSM4(rh, kb + (p * 16) * ARS + kk * 32 + b_offd);
                uint32_t b0[2] = {rh[0], rh[1]}, b1[2] = {rh[2], rh[3]};
                MMA16816(sacc[2 * p], a, b0);
                MMA16816(sacc[2 * p + 1], a, b1);
            }
        }

        // bias + online softmax (log2 domain -> exp2f)
        float mx0 = -3.0e38f, mx1 = -3.0e38f;
#pragma unroll
        for (int f = 0; f < 8; f++) {
            sacc[f][0] += bpre[f][0].x;
            sacc[f][1] += bpre[f][0].y;
            sacc[f][2] += bpre[f][1].x;
            sacc[f][3] += bpre[f][1].y;
            mx0 = fmaxf(mx0, fmaxf(sacc[f][0], sacc[f][1]));
            mx1 = fmaxf(mx1, fmaxf(sacc[f][2], sacc[f][3]));
        }
        mx0 = fmaxf(mx0, __shfl_xor_sync(0xffffffffu, mx0, 1));
        mx0 = fmaxf(mx0, __shfl_xor_sync(0xffffffffu, mx0, 2));
        mx1 = fmaxf(mx1, __shfl_xor_sync(0xffffffffu, mx1, 1));
        mx1 = fmaxf(mx1, __shfl_xor_sync(0xffffffffu, mx1, 2));

        float mn0 = fmaxf(m0r, mx0), mn1 = fmaxf(m1r, mx1);
        float fac0 = exp2f(m0r - mn0), fac1 = exp2f(m1r - mn1);
        m0r = mn0; m1r = mn1;

        uint32_t pa[4][4];
        float sum0 = 0.f, sum1 = 0.f;
#pragma unroll
        for (int f = 0; f < 8; f++) {
            float p0 = exp2f(sacc[f][0] - mn0);
            float p1 = exp2f(sacc[f][1] - mn0);
            float p2 = exp2f(sacc[f][2] - mn1);
            float p3 = exp2f(sacc[f][3] - mn1);
            sum0 += p0 + p1; sum1 += p2 + p3;
            int jc = f >> 1, half = (f & 1) << 1;
            pa[jc][half]     = pack_h2(p0, p1);
            pa[jc][half + 1] = pack_h2(p2, p3);
        }
        sum0 += __shfl_xor_sync(0xffffffffu, sum0, 1);
        sum0 += __shfl_xor_sync(0xffffffffu, sum0, 2);
        sum1 += __shfl_xor_sync(0xffffffffu, sum1, 1);
        sum1 += __shfl_xor_sync(0xffffffffu, sum1, 2);
        l0 = l0 * fac0 + sum0;
        l1 = l1 * fac1 + sum1;

#pragma unroll
        for (int f = 0; f < 8; f++) {
            O[f][0] *= fac0; O[f][1] *= fac0;
            O[f][2] *= fac1; O[f][3] *= fac1;
        }

        const uint32_t vb = kb + KVT64;
#pragma unroll
        for (int jc = 0; jc < 4; jc++) {
#pragma unroll
            for (int dbk = 0; dbk < 4; dbk++) {
                uint32_t rh[4];
                LDSM4T(rh, vb + (jc * 16) * ARS + dbk * 32 + v_off);
                uint32_t bh0[2] = {rh[0], rh[1]}, bh1[2] = {rh[2], rh[3]};
                MMA16816(O[2 * dbk], pa[jc], bh0);
                MMA16816(O[2 * dbk + 1], pa[jc], bh1);
            }
        }
        __syncthreads();
    }

    // epilogue: normalize, store ctx single fp16
    const float inv0 = 1.0f / l0, inv1 = 1.0f / l1;
    const size_t row0 = (size_t)(b * LEN + i0 + wid * 16 + r0) * DM;
    const size_t row1 = row0 + 8 * DM;
    const int colb = h * 64 + c0;
#pragma unroll
    for (int f = 0; f < 8; f++) {
        *(uint32_t*)(ctx + row0 + colb + f * 8) = pack_h2(O[f][0] * inv0, O[f][1] * inv0);
        *(uint32_t*)(ctx + row1 + colb + f * 8) = pack_h2(O[f][2] * inv1, O[f][3] * inv1);
    }
}

// ---------------- launch ----------------
extern "C" void kernel_launch(void* const* d_in, const int* in_sizes, int n_in,
                              void* d_out, int out_size) {
    const float* x              = (const float*)d_in[0];
    const float* pf             = (const float*)d_in[1];
    const int*   ids            = (const int*)d_in[2];
    const float* ss             = (const float*)d_in[3];
    const float* Wq             = (const float*)d_in[4];
    const float* Wk             = (const float*)d_in[5];
    const float* Wv             = (const float*)d_in[6];
    const float* Wo             = (const float*)d_in[7];
    const float* bo             = (const float*)d_in[8];
    const float* inter_mat      = (const float*)d_in[10];
    const float* ss_w           = (const float*)d_in[11];
    const float* physics_scale  = (const float*)d_in[12];
    const float* distance_decay = (const float*)d_in[13];
    float* out = (float*)d_out;

    float *biasb, *proj;
    __half *a, *w, *qkv;
    cudaGetSymbolAddress((void**)&biasb, g_bias);
    cudaGetSymbolAddress((void**)&proj, g_proj);
    cudaGetSymbolAddress((void**)&a,    g_a);
    cudaGetSymbolAddress((void**)&w,    g_w);
    cudaGetSymbolAddress((void**)&qkv,  g_qkv);

    cudaFuncSetAttribute(gemm_mma, cudaFuncAttributeMaxDynamicSharedMemorySize, 2 * STG);
    cudaFuncSetAttribute(attn_mma, cudaFuncAttributeMaxDynamicSharedMemorySize, ATTN_SMEM);

    static cudaStream_t s_side = nullptr;
    static cudaEvent_t ev_fork = nullptr, evG[4] = {}, evA[4] = {};
    if (s_side == nullptr) {
        cudaStreamCreateWithFlags(&s_side, cudaStreamNonBlocking);
        cudaEventCreateWithFlags(&ev_fork, cudaEventDisableTiming);
        for (int i = 0; i < 4; i++) {
            cudaEventCreateWithFlags(&evG[i], cudaEventDisableTiming);
            cudaEventCreateWithFlags(&evA[i], cudaEventDisableTiming);
        }
    }

    // fork: bias path on side stream (proj + per-batch bias)
    cudaEventRecord(ev_fork, 0);
    cudaStreamWaitEvent(s_side, ev_fork, 0);
    proj_kernel<<<256, 256, 0, s_side>>>(ss, ss_w, proj);
    for (int bb = 0; bb < 4; bb++)
        bias_kernel<<<dim3(32, 32, 1), dim3(32, 32), 0, s_side>>>(
            pf, ids, inter_mat, proj, physics_scale, distance_decay, biasb, bb);

    // main: converts + per-batch QKV GEMM chunks (q cols pre-scaled by 0.125*log2e)
    conv4_kernel<<<dim3(1024, 4), 256>>>((const float4*)Wq, (const float4*)Wk,
                                         (const float4*)Wv, (const float4*)Wo, (__half2*)w);
    conv_kernel<<<4096, 256>>>((const float4*)x, (__half2*)a, 1024 * 1024);

    for (int bb = 0; bb < 4; bb++) {
        gemm_mma<<<dim3(24, 8), 256, 2 * STG>>>(a, w, nullptr, nullptr, qkv,
                                                3072, 0, bb * 1024, 1024);
        cudaEventRecord(evG[bb], 0);
    }

    // side: per-batch attention, each waiting only on its own gemm chunk
    for (int bb = 0; bb < 4; bb++) {
        cudaStreamWaitEvent(s_side, evG[bb], 0);
        attn_mma<<<dim3(8, NH, 1), 256, ATTN_SMEM, s_side>>>(qkv, biasb, a, bb);
        cudaEventRecord(evA[bb], s_side);
    }

    // main: per-batch out-proj, each waiting only on its own attn chunk
    for (int bb = 0; bb < 4; bb++) {
        cudaStreamWaitEvent(0, evA[bb], 0);
        gemm_mma<<<dim3(8, 8), 256, 2 * STG>>>(a, w, bo, out, nullptr,
                                               1024, 3072, bb * 1024, 0);
    }
}